// round 4
// baseline (speedup 1.0000x reference)
#include <cuda_runtime.h>
#include <cuda.h>
#include <cuda_bf16.h>
#include <cuda_fp16.h>
#include <cstdint>

// Problem dims (fixed by reference)
#define BB 16
#define TT 4096
#define DD 512           // K dim of GEMM / feature dim
#define EE 512           // N dim of GEMM
#define MTOT (BB*TT)     // 65536 rows

// ---------------- scratch (device globals; no allocation) ----------------
__device__ __half g_Whf[EE * DD];   // transposed W in fp16: Whf[e][d]
__device__ float g_scores[MTOT];    // scores[b*T + t]
__device__ float g_stats[BB * 2];   // {max, 1/sumexp} per batch

// ---------------- PTX helpers ----------------
__device__ __forceinline__ uint32_t smem_u32(const void* p) {
    uint32_t a;
    asm("{ .reg .u64 t; cvta.to.shared.u64 t, %1; cvt.u32.u64 %0, t; }" : "=r"(a) : "l"(p));
    return a;
}

#define MBARRIER_INIT(addr, cnt) \
    asm volatile("mbarrier.init.shared.b64 [%0], %1;" :: "r"((uint32_t)(addr)), "r"((uint32_t)(cnt)) : "memory")

#define MBARRIER_EXPECT_TX(addr, bytes) \
    asm volatile("mbarrier.arrive.expect_tx.shared.b64 _, [%0], %1;" :: "r"((uint32_t)(addr)), "r"((uint32_t)(bytes)) : "memory")

#define MBARRIER_WAIT_PARITY(mbar_smem_addr, phase_parity) do { \
    uint32_t _mbar = (uint32_t)(mbar_smem_addr); \
    uint32_t _parity = (uint32_t)(phase_parity); \
    uint32_t _done; \
    asm volatile( \
        "{\n\t" \
        ".reg .pred p;\n\t" \
        "mbarrier.try_wait.parity.acquire.cta.shared::cta.b64 p, [%1], %2;\n\t" \
        "selp.b32 %0, 1, 0, p;\n\t" \
        "}" \
        : "=r"(_done) : "r"(_mbar), "r"(_parity) : "memory"); \
    if (!_done) { \
        asm volatile( \
            "{\n\t" \
            ".reg .pred P1;\n\t" \
            "WAIT_LOOP_%=:\n\t" \
            "mbarrier.try_wait.parity.acquire.cta.shared::cta.b64 P1, [%0], %1, 0x989680;\n\t" \
            "@P1 bra.uni WAIT_DONE_%=;\n\t" \
            "bra.uni WAIT_LOOP_%=;\n\t" \
            "WAIT_DONE_%=:\n\t" \
            "}" \
            :: "r"(_mbar), "r"(_parity) : "memory"); \
    } \
} while(0)

#define TMA_LOAD_2D(smem_addr, map_ptr, c0, c1, mbar) \
    asm volatile("cp.async.bulk.tensor.2d.shared::cta.global.tile.mbarrier::complete_tx::bytes " \
        "[%0], [%1, {%2, %3}], [%4];" \
        :: "r"((uint32_t)(smem_addr)), "l"(map_ptr), "r"((int)(c0)), "r"((int)(c1)), \
           "r"((uint32_t)(mbar)) : "memory")

__device__ __forceinline__ void ldsm_x4(uint32_t* r, uint32_t addr) {
    asm volatile("ldmatrix.sync.aligned.m8n8.x4.shared.b16 {%0,%1,%2,%3}, [%4];"
        : "=r"(r[0]), "=r"(r[1]), "=r"(r[2]), "=r"(r[3]) : "r"(addr));
}
// fp16 inputs, fp16 accumulate (2 packed regs)
__device__ __forceinline__ void mma_f16(uint32_t* d, const uint32_t* a, const uint32_t* b) {
    asm volatile("mma.sync.aligned.m16n8k16.row.col.f16.f16.f16.f16 "
        "{%0,%1}, {%2,%3,%4,%5}, {%6,%7}, {%0,%1};"
        : "+r"(d[0]), "+r"(d[1])
        : "r"(a[0]), "r"(a[1]), "r"(a[2]), "r"(a[3]), "r"(b[0]), "r"(b[1]));
}
__device__ __forceinline__ float tanh_approx(float x) {
    float r;
    asm("tanh.approx.f32 %0, %1;" : "=f"(r) : "f"(x));
    return r;
}

// ---------------- kernel 0: transpose + convert W -> g_Whf[e][d] fp16 --------
__global__ void k0_transpose(const float* __restrict__ W) {
    __shared__ float tile[32][33];
    int x0 = blockIdx.x * 32, y0 = blockIdx.y * 32;
    int tx = threadIdx.x & 31, ty = threadIdx.x >> 5;  // 256 threads = 32x8
#pragma unroll
    for (int i = 0; i < 32; i += 8) tile[ty + i][tx] = W[(y0 + ty + i) * EE + x0 + tx];
    __syncthreads();
#pragma unroll
    for (int i = 0; i < 32; i += 8)
        g_Whf[(x0 + ty + i) * DD + y0 + tx] = __float2half(tile[tx][ty + i]);
}

// ---------------- kernel 1: fused fp16 mma GEMM + tanh + dot(v) -> scores ----
// CTA: 128 rows of x. 256 threads = 8 warps, warp tile m16 x n32 (A held in
// REGISTERS for all of K=512). fp16 accumulation, promoted to fp32 every K=128.
// W streamed in N-chunks of 32 (TMA, double-buffered).
#define N_CHUNK  32
#define N_CHUNKS 16
#define W_CHUNK_BYTES 32768   // 32 n-rows x 512 k x 2B

// smem offsets
#define SM_FULL   0           // 2 mbarriers
#define SM_V      64          // 512 floats
#define SM_A      4096        // 128 rows x 512 k fp16, 8 sub-boxes of 128x128B
#define SM_W      135168      // 2 x 32768
#define SM_TOTAL1 200704

__device__ __forceinline__ uint32_t swz(uint32_t row, uint32_t col_bytes) {
    return row * 128u + (col_bytes ^ ((row & 7u) << 4));
}

__global__ void __launch_bounds__(256, 1) k1_gemm_scores(
    const __grid_constant__ CUtensorMap tma_w,
    const float* __restrict__ x,
    const float* __restrict__ att_v)
{
    extern __shared__ char smem[];
    uint32_t sb = smem_u32(smem);
    const int tid = threadIdx.x, lane = tid & 31, wid = tid >> 5;

    float* vsh = (float*)(smem + SM_V);

    if (tid == 0) {
        MBARRIER_INIT(sb + SM_FULL, 1);
        MBARRIER_INIT(sb + SM_FULL + 8, 1);
    }
    for (int i = tid; i < EE; i += 256) vsh[i] = att_v[i];
    __syncthreads();

    const int m0 = blockIdx.x * 128;

    // kick W chunks 0 and 1 (8 TMA sub-box loads each: 64k x 32n, SW128)
    if (tid == 0) {
#pragma unroll
        for (int s = 0; s < 2; s++) {
            MBARRIER_EXPECT_TX(sb + SM_FULL + 8 * s, W_CHUNK_BYTES);
#pragma unroll
            for (int kb = 0; kb < 8; kb++)
                TMA_LOAD_2D(sb + SM_W + s * W_CHUNK_BYTES + kb * 4096, &tma_w,
                            kb * 64, s * N_CHUNK, sb + SM_FULL + 8 * s);
        }
    }

    // load + convert A tile: x[m0:m0+128, 0:512] fp32 -> fp16 SW128 smem
    {
        const float4* xg = (const float4*)(x + (size_t)m0 * DD);
#pragma unroll 8
        for (int i = 0; i < 64; i++) {
            int idx = tid + i * 256;
            int r = idx >> 7, c4 = idx & 127;
            float4 f = xg[(size_t)r * 128 + c4];
            __half2 lo = __floats2half2_rn(f.x, f.y);
            __half2 hi = __floats2half2_rn(f.z, f.w);
            int k = c4 * 4;
            uint32_t off = (uint32_t)SM_A + (uint32_t)(k >> 6) * 16384u + swz(r, (k & 63) * 2);
            uint2 u;
            u.x = *reinterpret_cast<uint32_t*>(&lo);
            u.y = *reinterpret_cast<uint32_t*>(&hi);
            *reinterpret_cast<uint2*>(smem + off) = u;
        }
    }
    __syncthreads();

    // ---- pull this warp's A fragments into registers (whole K=512) ----
    uint32_t areg[8][4][4];
    {
        uint32_t row  = (uint32_t)wid * 16 + (lane & 15);
        uint32_t abase = sb + SM_A + row * 128u;
        uint32_t axor  = ((row & 7u) << 4) ^ ((uint32_t)(lane >> 4) << 4);
#pragma unroll
        for (int kb = 0; kb < 8; kb++)
#pragma unroll
            for (int kq = 0; kq < 4; kq++)
                ldsm_x4(areg[kb][kq], abase + (uint32_t)kb * 16384u + (((uint32_t)kq * 32u) ^ axor));
    }

    // B ldmatrix address pieces (x4 covers 16 n-rows x k16)
    uint32_t nrow_lo = (lane & 7u) + (((uint32_t)lane >> 4) << 3);
    uint32_t brow = nrow_lo * 128u;
    uint32_t bxor = ((((uint32_t)lane >> 3) & 1u) << 4) ^ ((nrow_lo & 7u) << 4);

    float score0 = 0.f, score1 = 0.f;

    for (int chunk = 0; chunk < N_CHUNKS; chunk++) {
        const int buf = chunk & 1;
        const int ph  = (chunk >> 1) & 1;
        const uint32_t wb = sb + SM_W + buf * W_CHUNK_BYTES;

        MBARRIER_WAIT_PARITY(sb + SM_FULL + 8 * buf, ph);

        float facc[4][4];
#pragma unroll
        for (int g = 0; g < 4; g++)
#pragma unroll
            for (int j = 0; j < 4; j++) facc[g][j] = 0.f;

        uint32_t dh[4][2];
#pragma unroll
        for (int g = 0; g < 4; g++) { dh[g][0] = 0u; dh[g][1] = 0u; }

        // K loop: 8 sub-boxes x 4 k16-steps; fp16 acc, promote every 2 boxes (K=128)
#pragma unroll
        for (int kb = 0; kb < 8; kb++) {
            const uint32_t wkb = wb + (uint32_t)kb * 4096u + brow;
#pragma unroll
            for (int kq = 0; kq < 4; kq++) {
                const uint32_t kc = (uint32_t)kq * 32u;
                uint32_t b0[4], b1[4];
                ldsm_x4(b0, wkb + (kc ^ bxor));          // n 0-15 of chunk
                ldsm_x4(b1, wkb + 2048u + (kc ^ bxor));  // n 16-31 of chunk
                mma_f16(dh[0], areg[kb][kq], b0);
                mma_f16(dh[1], areg[kb][kq], b0 + 2);
                mma_f16(dh[2], areg[kb][kq], b1);
                mma_f16(dh[3], areg[kb][kq], b1 + 2);
            }
            if (kb & 1) {  // promote fp16 partials -> fp32, reset fp16 acc
#pragma unroll
                for (int g = 0; g < 4; g++) {
                    float2 lo = __half22float2(*reinterpret_cast<__half2*>(&dh[g][0]));
                    float2 hi = __half22float2(*reinterpret_cast<__half2*>(&dh[g][1]));
                    facc[g][0] += lo.x; facc[g][1] += lo.y;
                    facc[g][2] += hi.x; facc[g][3] += hi.y;
                    dh[g][0] = 0u; dh[g][1] = 0u;
                }
            }
        }

        __syncthreads();  // all warps done reading this W buffer
        if (chunk + 2 < N_CHUNKS && tid == 0) {
            MBARRIER_EXPECT_TX(sb + SM_FULL + 8 * buf, W_CHUNK_BYTES);
#pragma unroll
            for (int kb = 0; kb < 8; kb++)
                TMA_LOAD_2D(wb + kb * 4096, &tma_w,
                            kb * 64, (chunk + 2) * N_CHUNK, sb + SM_FULL + 8 * buf);
        }

        // epilogue AFTER prefetch: tanh + dot with v (TMA flies underneath)
        {
            const int jb = chunk * N_CHUNK + (lane & 3) * 2;
#pragma unroll
            for (int g = 0; g < 4; g++) {
                float v0 = vsh[jb + g * 8];
                float v1 = vsh[jb + g * 8 + 1];
                score0 += tanh_approx(facc[g][0]) * v0 + tanh_approx(facc[g][1]) * v1;
                score1 += tanh_approx(facc[g][2]) * v0 + tanh_approx(facc[g][3]) * v1;
            }
        }
    }

    // reduce over n: lanes sharing a row differ only in (lane&3)
    score0 += __shfl_xor_sync(0xFFFFFFFF, score0, 1);
    score0 += __shfl_xor_sync(0xFFFFFFFF, score0, 2);
    score1 += __shfl_xor_sync(0xFFFFFFFF, score1, 1);
    score1 += __shfl_xor_sync(0xFFFFFFFF, score1, 2);
    if ((lane & 3) == 0) {
        int r = m0 + wid * 16 + (lane >> 2);
        g_scores[r]     = score0;
        g_scores[r + 8] = score1;
    }
}

// ---------------- kernel 2: per-batch softmax stats (max, 1/sumexp) ----------
__global__ void k2_stats() {
    int b = blockIdx.x;
    __shared__ float red[256];
    float m = -1e30f;
    for (int t = threadIdx.x; t < TT; t += 256) m = fmaxf(m, g_scores[b * TT + t]);
    red[threadIdx.x] = m; __syncthreads();
    for (int s = 128; s > 0; s >>= 1) {
        if (threadIdx.x < s) red[threadIdx.x] = fmaxf(red[threadIdx.x], red[threadIdx.x + s]);
        __syncthreads();
    }
    float mx = red[0]; __syncthreads();
    float sum = 0.0f;
    for (int t = threadIdx.x; t < TT; t += 256) sum += __expf(g_scores[b * TT + t] - mx);
    red[threadIdx.x] = sum; __syncthreads();
    for (int s = 128; s > 0; s >>= 1) {
        if (threadIdx.x < s) red[threadIdx.x] += red[threadIdx.x + s];
        __syncthreads();
    }
    if (threadIdx.x == 0) { g_stats[2 * b] = mx; g_stats[2 * b + 1] = 1.0f / red[0]; }
}

// ---------------- kernel 3: weighted-sum pooling (fp32, vectorized) ----------
// grid (16 t-groups of 64, 16 batches), 256 threads: two 128-thread halves,
// each half covers 32 t; thread owns one float4 d-column.
__global__ void __launch_bounds__(256) k3_pool(const float* __restrict__ x,
                                               float* __restrict__ out) {
    int b = blockIdx.y;
    int half = threadIdx.x >> 7;     // 0 or 1
    int dt   = threadIdx.x & 127;    // float4 column
    int t0 = blockIdx.x * 64;
    __shared__ float w_s[64];
    float mx = g_stats[2 * b], inv = g_stats[2 * b + 1];
    if (threadIdx.x < 64)
        w_s[threadIdx.x] = __expf(g_scores[b * TT + t0 + threadIdx.x] - mx) * inv;
    __syncthreads();
    const float4* xp = (const float4*)(x + ((size_t)b * TT + t0 + half * 32) * DD) + dt;
    const float* wp = w_s + half * 32;
    float ax = 0.f, ay = 0.f, az = 0.f, aw = 0.f;
    float bx_ = 0.f, by = 0.f, bz = 0.f, bw = 0.f;
#pragma unroll 16
    for (int i = 0; i < 32; i += 2) {
        float4 f0 = xp[(size_t)i * 128];
        float4 f1 = xp[(size_t)(i + 1) * 128];
        float w0 = wp[i], w1 = wp[i + 1];
        ax = fmaf(w0, f0.x, ax); ay = fmaf(w0, f0.y, ay);
        az = fmaf(w0, f0.z, az); aw = fmaf(w0, f0.w, aw);
        bx_ = fmaf(w1, f1.x, bx_); by = fmaf(w1, f1.y, by);
        bz = fmaf(w1, f1.z, bz); bw = fmaf(w1, f1.w, bw);
    }
    float* o = out + b * DD + dt * 4;
    atomicAdd(o + 0, ax + bx_); atomicAdd(o + 1, ay + by);
    atomicAdd(o + 2, az + bz); atomicAdd(o + 3, aw + bw);
}

// ---------------- host ----------------
typedef CUresult (*EncodeTiledFn)(
    CUtensorMap*, CUtensorMapDataType, cuuint32_t, void*,
    const cuuint64_t*, const cuuint64_t*, const cuuint32_t*, const cuuint32_t*,
    CUtensorMapInterleave, CUtensorMapSwizzle, CUtensorMapL2promotion, CUtensorMapFloatOOBfill);

extern "C" void kernel_launch(void* const* d_in, const int* in_sizes, int n_in,
                              void* d_out, int out_size) {
    const float* x = (const float*)d_in[0];
    const float* W = (const float*)d_in[1];
    const float* v = (const float*)d_in[2];
    float* out = (float*)d_out;

    EncodeTiledFn encode = nullptr;
    cudaDriverEntryPointQueryResult qres;
    cudaGetDriverEntryPointByVersion("cuTensorMapEncodeTiled", (void**)&encode,
                                     12000, cudaEnableDefault, &qres);

    void* whf_ptr = nullptr;
    cudaGetSymbolAddress(&whf_ptr, g_Whf);

    k0_transpose<<<dim3(16, 16), 256>>>(W);

    CUtensorMap tma_w{};
    if (encode) {
        cuuint64_t dims[2]    = { (cuuint64_t)DD, (cuuint64_t)EE };
        cuuint64_t strides[1] = { (cuuint64_t)DD * sizeof(__half) };
        cuuint32_t box[2]     = { 64, N_CHUNK };
        cuuint32_t es[2]      = { 1, 1 };
        encode(&tma_w, CU_TENSOR_MAP_DATA_TYPE_FLOAT16, 2, whf_ptr,
               dims, strides, box, es,
               CU_TENSOR_MAP_INTERLEAVE_NONE, CU_TENSOR_MAP_SWIZZLE_128B,
               CU_TENSOR_MAP_L2_PROMOTION_L2_128B, CU_TENSOR_MAP_FLOAT_OOB_FILL_NONE);
    }

    cudaFuncSetAttribute(k1_gemm_scores, cudaFuncAttributeMaxDynamicSharedMemorySize, SM_TOTAL1);
    k1_gemm_scores<<<MTOT / 128, 256, SM_TOTAL1>>>(tma_w, x, v);

    k2_stats<<<BB, 256>>>();

    cudaMemsetAsync(d_out, 0, (size_t)out_size * sizeof(float));
    k3_pool<<<dim3(TT / 64, BB), 256>>>(x, out);
}

// round 5
// speedup vs baseline: 1.1570x; 1.1570x over previous
#include <cuda_runtime.h>
#include <cuda.h>
#include <cuda_fp16.h>
#include <cstdint>

// Problem dims (fixed by reference)
#define BB 16
#define TT 4096
#define DD 512           // K dim of GEMM / feature dim
#define EE 512           // N dim of GEMM
#define MTOT (BB*TT)     // 65536 rows
#define CTA_M 64
#define NCTAS (MTOT/CTA_M)   // 1024
#define CTAS_PER_B (TT/CTA_M) // 64

// ---------------- scratch (device globals; no allocation) ----------------
__device__ __half g_Whf[EE * DD];       // transposed W in fp16: Whf[e][d]
__device__ float g_part[NCTAS * DD];    // per-CTA partial weighted sums
__device__ float g_pmax[NCTAS];         // per-CTA score max
__device__ float g_psum[NCTAS];         // per-CTA sum exp(score - max)

// ---------------- PTX helpers ----------------
__device__ __forceinline__ uint32_t smem_u32(const void* p) {
    uint32_t a;
    asm("{ .reg .u64 t; cvta.to.shared.u64 t, %1; cvt.u32.u64 %0, t; }" : "=r"(a) : "l"(p));
    return a;
}

#define MBARRIER_INIT(addr, cnt) \
    asm volatile("mbarrier.init.shared.b64 [%0], %1;" :: "r"((uint32_t)(addr)), "r"((uint32_t)(cnt)) : "memory")

#define MBARRIER_EXPECT_TX(addr, bytes) \
    asm volatile("mbarrier.arrive.expect_tx.shared.b64 _, [%0], %1;" :: "r"((uint32_t)(addr)), "r"((uint32_t)(bytes)) : "memory")

#define MBARRIER_WAIT_PARITY(mbar_smem_addr, phase_parity) do { \
    uint32_t _mbar = (uint32_t)(mbar_smem_addr); \
    uint32_t _parity = (uint32_t)(phase_parity); \
    uint32_t _done; \
    asm volatile( \
        "{\n\t" \
        ".reg .pred p;\n\t" \
        "mbarrier.try_wait.parity.acquire.cta.shared::cta.b64 p, [%1], %2;\n\t" \
        "selp.b32 %0, 1, 0, p;\n\t" \
        "}" \
        : "=r"(_done) : "r"(_mbar), "r"(_parity) : "memory"); \
    if (!_done) { \
        asm volatile( \
            "{\n\t" \
            ".reg .pred P1;\n\t" \
            "WAIT_LOOP_%=:\n\t" \
            "mbarrier.try_wait.parity.acquire.cta.shared::cta.b64 P1, [%0], %1, 0x989680;\n\t" \
            "@P1 bra.uni WAIT_DONE_%=;\n\t" \
            "bra.uni WAIT_LOOP_%=;\n\t" \
            "WAIT_DONE_%=:\n\t" \
            "}" \
            :: "r"(_mbar), "r"(_parity) : "memory"); \
    } \
} while(0)

#define TMA_LOAD_2D(smem_addr, map_ptr, c0, c1, mbar) \
    asm volatile("cp.async.bulk.tensor.2d.shared::cta.global.tile.mbarrier::complete_tx::bytes " \
        "[%0], [%1, {%2, %3}], [%4];" \
        :: "r"((uint32_t)(smem_addr)), "l"(map_ptr), "r"((int)(c0)), "r"((int)(c1)), \
           "r"((uint32_t)(mbar)) : "memory")

__device__ __forceinline__ void ldsm_x4(uint32_t* r, uint32_t addr) {
    asm volatile("ldmatrix.sync.aligned.m8n8.x4.shared.b16 {%0,%1,%2,%3}, [%4];"
        : "=r"(r[0]), "=r"(r[1]), "=r"(r[2]), "=r"(r[3]) : "r"(addr));
}
// fp16 inputs, fp32 accumulate
__device__ __forceinline__ void mma_f16f32(float* d, const uint32_t* a, const uint32_t* b) {
    asm volatile("mma.sync.aligned.m16n8k16.row.col.f32.f16.f16.f32 "
        "{%0,%1,%2,%3}, {%4,%5,%6,%7}, {%8,%9}, {%0,%1,%2,%3};"
        : "+f"(d[0]), "+f"(d[1]), "+f"(d[2]), "+f"(d[3])
        : "r"(a[0]), "r"(a[1]), "r"(a[2]), "r"(a[3]), "r"(b[0]), "r"(b[1]));
}
__device__ __forceinline__ float tanh_approx(float x) {
    float r;
    asm("tanh.approx.f32 %0, %1;" : "=f"(r) : "f"(x));
    return r;
}

// ---------------- kernel 0: transpose + convert W -> g_Whf[e][d] fp16 --------
__global__ void k0_transpose(const float* __restrict__ W) {
    __shared__ float tile[32][33];
    int x0 = blockIdx.x * 32, y0 = blockIdx.y * 32;
    int tx = threadIdx.x & 31, ty = threadIdx.x >> 5;  // 256 threads = 32x8
#pragma unroll
    for (int i = 0; i < 32; i += 8) tile[ty + i][tx] = W[(y0 + ty + i) * EE + x0 + tx];
    __syncthreads();
#pragma unroll
    for (int i = 0; i < 32; i += 8)
        g_Whf[(x0 + ty + i) * DD + y0 + tx] = __float2half(tile[tx][ty + i]);
}

// ---------------- kernel 1: fused GEMM + tanh + dot(v) + online-softmax pool -
// CTA: 64 rows. 128 threads = 4 warps, warp tile m16 x n16 (A in registers for
// all K=512). W streamed in N-chunks of 16 (TMA, double-buffered).
// Epilogue: per-CTA softmax partials + weighted x pooling (x re-read from L2).
#define N_CHUNK  16
#define N_CHUNKS 32
#define W_CHUNK_BYTES 16384   // 16 n-rows x 512 k x 2B

// smem offsets
#define SM_FULL   0           // 2 mbarriers
#define SM_V      64          // 512 floats -> 2112
#define SM_SC     2112        // 64 floats  -> 2368
#define SM_ES     2368        // 64 floats  -> 2624
#define SM_A      4096        // 64 rows x 512 k fp16 = 64KB (8 boxes of 8KB)
#define SM_W      69632       // 2 x 16384
#define SM_TOTAL1 102400

__device__ __forceinline__ uint32_t swz(uint32_t row, uint32_t col_bytes) {
    return row * 128u + (col_bytes ^ ((row & 7u) << 4));
}

__global__ void __launch_bounds__(128, 2) k1_gemm_scores(
    const __grid_constant__ CUtensorMap tma_w,
    const float* __restrict__ x,
    const float* __restrict__ att_v)
{
    extern __shared__ char smem[];
    uint32_t sb = smem_u32(smem);
    const int tid = threadIdx.x, lane = tid & 31, wid = tid >> 5;

    float* vsh = (float*)(smem + SM_V);
    float* ssc = (float*)(smem + SM_SC);
    float* esh = (float*)(smem + SM_ES);

    if (tid == 0) {
        MBARRIER_INIT(sb + SM_FULL, 1);
        MBARRIER_INIT(sb + SM_FULL + 8, 1);
    }
    for (int i = tid; i < EE; i += 128) vsh[i] = att_v[i];
    __syncthreads();

    const int cta = blockIdx.x;
    const int m0 = cta * CTA_M;

    // kick W chunks 0 and 1 (8 TMA boxes each: 64k x 16n, SW128)
    if (tid == 0) {
#pragma unroll
        for (int s = 0; s < 2; s++) {
            MBARRIER_EXPECT_TX(sb + SM_FULL + 8 * s, W_CHUNK_BYTES);
#pragma unroll
            for (int kb = 0; kb < 8; kb++)
                TMA_LOAD_2D(sb + SM_W + s * W_CHUNK_BYTES + kb * 2048, &tma_w,
                            kb * 64, s * N_CHUNK, sb + SM_FULL + 8 * s);
        }
    }

    // load + convert A tile: x[m0:m0+64, 0:512] fp32 -> fp16 SW128 smem
    {
        const float4* xg = (const float4*)(x + (size_t)m0 * DD);
#pragma unroll 8
        for (int i = 0; i < 64; i++) {
            int idx = tid + i * 128;
            int r = idx >> 7, c4 = idx & 127;
            float4 f = xg[(size_t)r * 128 + c4];
            __half2 lo = __floats2half2_rn(f.x, f.y);
            __half2 hi = __floats2half2_rn(f.z, f.w);
            int k = c4 * 4;
            uint32_t off = (uint32_t)SM_A + (uint32_t)(k >> 6) * 8192u + swz(r, (k & 63) * 2);
            uint2 u;
            u.x = *reinterpret_cast<uint32_t*>(&lo);
            u.y = *reinterpret_cast<uint32_t*>(&hi);
            *reinterpret_cast<uint2*>(smem + off) = u;
        }
    }
    __syncthreads();

    // ---- pull this warp's A fragments into registers (whole K=512) ----
    uint32_t areg[8][4][4];
    {
        uint32_t row   = (uint32_t)wid * 16 + (lane & 15);
        uint32_t abase = sb + SM_A + row * 128u;
        uint32_t axor  = ((row & 7u) << 4) ^ ((uint32_t)(lane >> 4) << 4);
#pragma unroll
        for (int kb = 0; kb < 8; kb++)
#pragma unroll
            for (int kq = 0; kq < 4; kq++)
                ldsm_x4(areg[kb][kq], abase + (uint32_t)kb * 8192u + (((uint32_t)kq * 32u) ^ axor));
    }

    // B ldmatrix address pieces (x4 covers 16 n-rows x k16)
    uint32_t nrow_lo = (lane & 7u) + (((uint32_t)lane >> 4) << 3);
    uint32_t brow = nrow_lo * 128u;
    uint32_t bxor = ((((uint32_t)lane >> 3) & 1u) << 4) ^ ((nrow_lo & 7u) << 4);

    float score0 = 0.f, score1 = 0.f;

    for (int chunk = 0; chunk < N_CHUNKS; chunk++) {
        const int buf = chunk & 1;
        const int ph  = (chunk >> 1) & 1;
        const uint32_t wb = sb + SM_W + buf * W_CHUNK_BYTES;

        MBARRIER_WAIT_PARITY(sb + SM_FULL + 8 * buf, ph);

        float acc[2][4];
#pragma unroll
        for (int g = 0; g < 2; g++)
#pragma unroll
            for (int j = 0; j < 4; j++) acc[g][j] = 0.f;

        // K loop: 8 boxes x 4 k16-steps
#pragma unroll
        for (int kb = 0; kb < 8; kb++) {
            const uint32_t wkb = wb + (uint32_t)kb * 2048u + brow;
#pragma unroll
            for (int kq = 0; kq < 4; kq++) {
                const uint32_t kc = (uint32_t)kq * 32u;
                uint32_t b0[4];
                ldsm_x4(b0, wkb + (kc ^ bxor));       // n 0-15 of chunk
                mma_f16f32(acc[0], areg[kb][kq], b0);
                mma_f16f32(acc[1], areg[kb][kq], b0 + 2);
            }
        }

        __syncthreads();  // all warps done reading this W buffer
        if (chunk + 2 < N_CHUNKS && tid == 0) {
            MBARRIER_EXPECT_TX(sb + SM_FULL + 8 * buf, W_CHUNK_BYTES);
#pragma unroll
            for (int kb = 0; kb < 8; kb++)
                TMA_LOAD_2D(wb + kb * 2048, &tma_w,
                            kb * 64, (chunk + 2) * N_CHUNK, sb + SM_FULL + 8 * buf);
        }

        // epilogue after prefetch: tanh + dot with v (TMA flies underneath)
        {
            const int jb = chunk * N_CHUNK + (lane & 3) * 2;
#pragma unroll
            for (int g = 0; g < 2; g++) {
                float v0 = vsh[jb + g * 8];
                float v1 = vsh[jb + g * 8 + 1];
                score0 += tanh_approx(acc[g][0]) * v0 + tanh_approx(acc[g][1]) * v1;
                score1 += tanh_approx(acc[g][2]) * v0 + tanh_approx(acc[g][3]) * v1;
            }
        }
    }

    // reduce over n: lanes sharing a row differ only in (lane&3)
    score0 += __shfl_xor_sync(0xFFFFFFFF, score0, 1);
    score0 += __shfl_xor_sync(0xFFFFFFFF, score0, 2);
    score1 += __shfl_xor_sync(0xFFFFFFFF, score1, 1);
    score1 += __shfl_xor_sync(0xFFFFFFFF, score1, 2);
    if ((lane & 3) == 0) {
        int r = wid * 16 + (lane >> 2);
        ssc[r]     = score0;
        ssc[r + 8] = score1;
    }
    __syncthreads();

    // ---- online-softmax pooling partials for this CTA's 64 rows ----
    // local max (each thread computes redundantly; smem broadcasts are cheap)
    float m_c = -1e30f;
#pragma unroll
    for (int t = 0; t < 64; t++) m_c = fmaxf(m_c, ssc[t]);
    if (tid < 64) esh[tid] = __expf(ssc[tid] - m_c);
    __syncthreads();

    if (wid == 0) {  // sum of exps + stats store
        float s = esh[lane] + esh[lane + 32];
        s += __shfl_xor_sync(0xFFFFFFFF, s, 16);
        s += __shfl_xor_sync(0xFFFFFFFF, s, 8);
        s += __shfl_xor_sync(0xFFFFFFFF, s, 4);
        s += __shfl_xor_sync(0xFFFFFFFF, s, 2);
        s += __shfl_xor_sync(0xFFFFFFFF, s, 1);
        if (lane == 0) { g_pmax[cta] = m_c; g_psum[cta] = s; }
    }

    // partial weighted sum: thread owns float4 d-column; x re-read (L2 hit)
    {
        const float4* xp = (const float4*)(x + (size_t)m0 * DD) + tid;
        float ax = 0.f, ay = 0.f, az = 0.f, aw = 0.f;
#pragma unroll 8
        for (int t = 0; t < 64; t++) {
            float4 f = xp[(size_t)t * 128];
            float w = esh[t];
            ax = fmaf(w, f.x, ax); ay = fmaf(w, f.y, ay);
            az = fmaf(w, f.z, az); aw = fmaf(w, f.w, aw);
        }
        float4 o; o.x = ax; o.y = ay; o.z = az; o.w = aw;
        ((float4*)(g_part + (size_t)cta * DD))[tid] = o;
    }
}

// ---------------- kernel 2: combine per-CTA partials -> out ------------------
// grid BB, 512 threads; thread owns one d.
__global__ void __launch_bounds__(512) k2_combine(float* __restrict__ out) {
    __shared__ float fm[64], fc[64];
    __shared__ float denom_s;
    const int b = blockIdx.x, tid = threadIdx.x;

    if (tid < 64) fm[tid] = g_pmax[b * CTAS_PER_B + tid];
    __syncthreads();
    float M = -1e30f;
#pragma unroll
    for (int c = 0; c < 64; c++) M = fmaxf(M, fm[c]);
    if (tid < 64) fc[tid] = __expf(fm[tid] - M);
    __syncthreads();
    if (tid < 32) {
        float s = fc[tid] * g_psum[b * CTAS_PER_B + tid]
                + fc[tid + 32] * g_psum[b * CTAS_PER_B + tid + 32];
        s += __shfl_xor_sync(0xFFFFFFFF, s, 16);
        s += __shfl_xor_sync(0xFFFFFFFF, s, 8);
        s += __shfl_xor_sync(0xFFFFFFFF, s, 4);
        s += __shfl_xor_sync(0xFFFFFFFF, s, 2);
        s += __shfl_xor_sync(0xFFFFFFFF, s, 1);
        if (tid == 0) denom_s = s;
    }
    __syncthreads();

    float num = 0.f;
#pragma unroll 8
    for (int c = 0; c < 64; c++)
        num += fc[c] * g_part[((size_t)(b * CTAS_PER_B + c)) * DD + tid];
    out[b * DD + tid] = num / denom_s;
}

// ---------------- host ----------------
typedef CUresult (*EncodeTiledFn)(
    CUtensorMap*, CUtensorMapDataType, cuuint32_t, void*,
    const cuuint64_t*, const cuuint64_t*, const cuuint32_t*, const cuuint32_t*,
    CUtensorMapInterleave, CUtensorMapSwizzle, CUtensorMapL2promotion, CUtensorMapFloatOOBfill);

extern "C" void kernel_launch(void* const* d_in, const int* in_sizes, int n_in,
                              void* d_out, int out_size) {
    const float* x = (const float*)d_in[0];
    const float* W = (const float*)d_in[1];
    const float* v = (const float*)d_in[2];
    float* out = (float*)d_out;

    EncodeTiledFn encode = nullptr;
    cudaDriverEntryPointQueryResult qres;
    cudaGetDriverEntryPointByVersion("cuTensorMapEncodeTiled", (void**)&encode,
                                     12000, cudaEnableDefault, &qres);

    void* whf_ptr = nullptr;
    cudaGetSymbolAddress(&whf_ptr, g_Whf);

    k0_transpose<<<dim3(16, 16), 256>>>(W);

    // TMA map for W: dims (k=512, n=512) fp16, box (64, 16), SW128
    CUtensorMap tma_w{};
    if (encode) {
        cuuint64_t dims[2]    = { (cuuint64_t)DD, (cuuint64_t)EE };
        cuuint64_t strides[1] = { (cuuint64_t)DD * sizeof(__half) };
        cuuint32_t box[2]     = { 64, N_CHUNK };
        cuuint32_t es[2]      = { 1, 1 };
        encode(&tma_w, CU_TENSOR_MAP_DATA_TYPE_FLOAT16, 2, whf_ptr,
               dims, strides, box, es,
               CU_TENSOR_MAP_INTERLEAVE_NONE, CU_TENSOR_MAP_SWIZZLE_128B,
               CU_TENSOR_MAP_L2_PROMOTION_L2_128B, CU_TENSOR_MAP_FLOAT_OOB_FILL_NONE);
    }

    cudaFuncSetAttribute(k1_gemm_scores, cudaFuncAttributeMaxDynamicSharedMemorySize, SM_TOTAL1);
    k1_gemm_scores<<<NCTAS, 128, SM_TOTAL1>>>(tma_w, x, v);

    k2_combine<<<BB, 512>>>(out);
}